// round 2
// baseline (speedup 1.0000x reference)
#include <cuda_runtime.h>

// ---------------------------------------------------------------------------
// Problem constants
// ---------------------------------------------------------------------------
constexpr int C_E   = 2048;
constexpr int C_NQ  = 64;
constexpr int C_NH  = 16;
constexpr int C_B   = 32;
constexpr int C_L   = 1024;           // MAXHW*MAXHW
constexpr int C_HQ  = C_NH * C_NQ;    // 1024

// ---------------------------------------------------------------------------
// Scratch (device globals; no allocation allowed)
// ---------------------------------------------------------------------------
__device__ float g_X  [ (size_t)C_B * C_L * C_E ];     // 32768 x 2048  (x, post-LN)
__device__ float g_S  [ (size_t)C_B * C_HQ * C_L ];    // scores / attn  [b][hq][l]
__device__ float g_T  [ (size_t)C_B * C_HQ * C_E ];    // t = attn @ X   [b][hq][e]
__device__ float g_A  [ (size_t)C_HQ * C_E ];          // folded q-side matrix
__device__ float g_P  [ (size_t)C_HQ * 1024 ];         // pe contribution [hq][pos]
__device__ float g_pe [ (size_t)1024 * C_E ];          // pe2d [pos][e]
__device__ float g_qln[ (size_t)C_NQ * C_E ];
__device__ float g_qh [ (size_t)C_NQ * C_E ];
__device__ float g_c  [ C_HQ ];                        // bk fold
__device__ float g_t2 [ (size_t)C_B * C_NQ * C_E ];    // per-head V projection
__device__ float g_o2 [ (size_t)C_B * C_NQ * C_E ];    // after wo
__device__ float g_bo2[ C_E ];                         // bo + wo @ bv

// ---------------------------------------------------------------------------
// Warp reduction helpers
// ---------------------------------------------------------------------------
__device__ __forceinline__ float warpSum(float v) {
#pragma unroll
    for (int o = 16; o > 0; o >>= 1) v += __shfl_xor_sync(0xffffffffu, v, o);
    return v;
}
__device__ __forceinline__ float warpMax(float v) {
#pragma unroll
    for (int o = 16; o > 0; o >>= 1) v = fmaxf(v, __shfl_xor_sync(0xffffffffu, v, o));
    return v;
}

// ---------------------------------------------------------------------------
// Generic tiled fp32 SGEMM.
//   C[i,j] = alpha * sum_k A[i,k] * op(B)[k,j] (+ bias[j])
//   TRANSB=1: B is (N,K) row-major (contract over last dim of both)  -> "NT"
//   TRANSB=0: B is (K,N) row-major                                   -> "NN"
//   Batched via blockIdx.z:  z -> (zd = z/zmod, zm = z%zmod)
//   operand offset = zd*s?d + zm*s?m
// ---------------------------------------------------------------------------
template<int BM, int BN, int BK, int TM, int TN, int TRANSB>
__global__ void __launch_bounds__((BM / TM) * (BN / TN))
sgemm_kernel(const float* __restrict__ Ag, int lda,
             const float* __restrict__ Bg, int ldb,
             float* __restrict__ Cg, int ldc,
             int M, int N, int K, float alpha,
             const float* __restrict__ bias,
             long long sAd, long long sAm,
             long long sBd, long long sBm,
             long long sCd, long long sCm, int zmod)
{
    constexpr int NTH   = (BM / TM) * (BN / TN);
    constexpr int TCOLS = BN / TN;
    static_assert((BM * BK / 4) % NTH == 0, "A load div");
    static_assert((BN * BK / 4) % NTH == 0, "B load div");

    __shared__ float As[BK][BM + 4];
    __shared__ float Bs[BK][BN + 4];

    int z  = blockIdx.z;
    int zd = z / zmod;
    int zm = z - zd * zmod;
    Ag += zd * sAd + zm * sAm;
    Bg += zd * sBd + zm * sBm;
    Cg += zd * sCd + zm * sCm;

    const int tid  = threadIdx.x;
    const int m0   = blockIdx.y * BM;
    const int n0   = blockIdx.x * BN;
    const int tr   = tid / TCOLS;
    const int tc   = tid - tr * TCOLS;
    const int row0 = tr * TM;
    const int col0 = tc * TN;

    float acc[TM][TN];
#pragma unroll
    for (int i = 0; i < TM; i++)
#pragma unroll
        for (int j = 0; j < TN; j++) acc[i][j] = 0.f;

    for (int k0 = 0; k0 < K; k0 += BK) {
        // ---- load A tile (BM x BK), stored transposed into As[k][m]
#pragma unroll
        for (int it = 0; it < BM * BK / 4 / NTH; it++) {
            int idx = tid + it * NTH;
            int r   = idx / (BK / 4);
            int kk  = (idx - r * (BK / 4)) * 4;
            int gr  = m0 + r; if (gr > M - 1) gr = M - 1;
            float4 v = *reinterpret_cast<const float4*>(Ag + (long long)gr * lda + k0 + kk);
            As[kk + 0][r] = v.x; As[kk + 1][r] = v.y;
            As[kk + 2][r] = v.z; As[kk + 3][r] = v.w;
        }
        // ---- load B tile
        if (TRANSB) {
#pragma unroll
            for (int it = 0; it < BN * BK / 4 / NTH; it++) {
                int idx = tid + it * NTH;
                int c   = idx / (BK / 4);
                int kk  = (idx - c * (BK / 4)) * 4;
                int gc  = n0 + c; if (gc > N - 1) gc = N - 1;
                float4 v = *reinterpret_cast<const float4*>(Bg + (long long)gc * ldb + k0 + kk);
                Bs[kk + 0][c] = v.x; Bs[kk + 1][c] = v.y;
                Bs[kk + 2][c] = v.z; Bs[kk + 3][c] = v.w;
            }
        } else {
#pragma unroll
            for (int it = 0; it < BK * BN / 4 / NTH; it++) {
                int idx = tid + it * NTH;
                int kk  = idx / (BN / 4);
                int c4  = (idx - kk * (BN / 4)) * 4;
                float4 v = *reinterpret_cast<const float4*>(Bg + (long long)(k0 + kk) * ldb + n0 + c4);
                *reinterpret_cast<float4*>(&Bs[kk][c4]) = v;
            }
        }
        __syncthreads();

#pragma unroll
        for (int k = 0; k < BK; k++) {
            float ar[TM], br[TN];
#pragma unroll
            for (int i = 0; i < TM; i += 4) {
                float4 t = *reinterpret_cast<const float4*>(&As[k][row0 + i]);
                ar[i] = t.x; ar[i + 1] = t.y; ar[i + 2] = t.z; ar[i + 3] = t.w;
            }
#pragma unroll
            for (int j = 0; j < TN; j += 4) {
                float4 t = *reinterpret_cast<const float4*>(&Bs[k][col0 + j]);
                br[j] = t.x; br[j + 1] = t.y; br[j + 2] = t.z; br[j + 3] = t.w;
            }
#pragma unroll
            for (int i = 0; i < TM; i++)
#pragma unroll
                for (int j = 0; j < TN; j++)
                    acc[i][j] = fmaf(ar[i], br[j], acc[i][j]);
        }
        __syncthreads();
    }

    // ---- epilogue (N is always a multiple of BN for all our calls)
#pragma unroll
    for (int i = 0; i < TM; i++) {
        int gr = m0 + row0 + i;
        if (gr < M) {
            float* cp = Cg + (long long)gr * ldc + n0 + col0;
#pragma unroll
            for (int j = 0; j < TN; j += 4) {
                int gc = n0 + col0 + j;
                float4 v;
                v.x = alpha * acc[i][j + 0] + (bias ? bias[gc + 0] : 0.f);
                v.y = alpha * acc[i][j + 1] + (bias ? bias[gc + 1] : 0.f);
                v.z = alpha * acc[i][j + 2] + (bias ? bias[gc + 2] : 0.f);
                v.w = alpha * acc[i][j + 3] + (bias ? bias[gc + 3] : 0.f);
                *reinterpret_cast<float4*>(cp + j) = v;
            }
        }
    }
}

// ---------------------------------------------------------------------------
// LayerNorm over rows of width 2048.  256 threads/row, 8 elems/thread.
// Safe for in == out.
// ---------------------------------------------------------------------------
__global__ void ln_kernel(const float* __restrict__ in, float* __restrict__ outp,
                          const float* __restrict__ gam, const float* __restrict__ bet)
{
    __shared__ float sh[8];
    __shared__ float s_mu, s_rs;
    const int row = blockIdx.x;
    const int t   = threadIdx.x;
    const float* x = in   + (long long)row * 2048;
    float*       y = outp + (long long)row * 2048;

    float v[8];
    float s = 0.f;
#pragma unroll
    for (int i = 0; i < 2; i++) {
        float4 f = *reinterpret_cast<const float4*>(x + (t + i * 256) * 4);
        v[i * 4 + 0] = f.x; v[i * 4 + 1] = f.y; v[i * 4 + 2] = f.z; v[i * 4 + 3] = f.w;
        s += f.x + f.y + f.z + f.w;
    }
    s = warpSum(s);
    if ((t & 31) == 0) sh[t >> 5] = s;
    __syncthreads();
    if (t == 0) {
        float tot = 0.f;
#pragma unroll
        for (int i = 0; i < 8; i++) tot += sh[i];
        s_mu = tot * (1.f / 2048.f);
    }
    __syncthreads();
    const float mu = s_mu;
    float q = 0.f;
#pragma unroll
    for (int i = 0; i < 8; i++) { float d = v[i] - mu; q += d * d; }
    q = warpSum(q);
    __syncthreads();               // protect sh reuse
    if ((t & 31) == 0) sh[t >> 5] = q;
    __syncthreads();
    if (t == 0) {
        float tot = 0.f;
#pragma unroll
        for (int i = 0; i < 8; i++) tot += sh[i];
        s_rs = rsqrtf(tot * (1.f / 2048.f) + 1e-5f);
    }
    __syncthreads();
    const float rs = s_rs;
#pragma unroll
    for (int i = 0; i < 2; i++) {
        int idx = (t + i * 256) * 4;
        float4 g4 = *reinterpret_cast<const float4*>(gam + idx);
        float4 b4 = *reinterpret_cast<const float4*>(bet + idx);
        float4 o;
        o.x = (v[i * 4 + 0] - mu) * rs * g4.x + b4.x;
        o.y = (v[i * 4 + 1] - mu) * rs * g4.y + b4.y;
        o.z = (v[i * 4 + 2] - mu) * rs * g4.z + b4.z;
        o.w = (v[i * 4 + 3] - mu) * rs * g4.w + b4.w;
        *reinterpret_cast<float4*>(y + idx) = o;
    }
}

// ---------------------------------------------------------------------------
// pe2d[pos][e] for pos = row*32 + col
// e in [0,512):    sin(row * om(e))
// e in [512,1024): cos(row * om(e-512))
// e in [1024,1536):sin(col * om(e-1024))
// e in [1536,2048):cos(col * om(e-1536))
// om(i) = 10000^{-i/512}
// ---------------------------------------------------------------------------
__global__ void pe_kernel(float* __restrict__ pe)
{
    const int pos = blockIdx.x;
    const int r   = pos >> 5;
    const int cc  = pos & 31;
    const int t   = threadIdx.x;
    const float k = -9.210340371976184f / 512.f;   // -ln(10000)/512
#pragma unroll
    for (int i = 0; i < 8; i++) {
        int e  = t + i * 256;
        int p  = (e < 1024) ? r : cc;
        int ee = e & 1023;
        float val;
        if (ee < 512) val = sinf((float)p * expf((float)ee * k));
        else          val = cosf((float)p * expf((float)(ee - 512) * k));
        pe[(long long)pos * 2048 + e] = val;
    }
}

// c[hq] = (1/sqrt(DH)) * sum_d qh[q, h*128+d] * bk[h*128+d]
__global__ void c_kernel(const float* __restrict__ qh, const float* __restrict__ bk,
                         float* __restrict__ cvec)
{
    int hq = blockIdx.x * blockDim.x + threadIdx.x;
    if (hq >= 1024) return;
    int h = hq >> 6, q = hq & 63;
    const float* qr = qh + (long long)q * 2048 + h * 128;
    const float* br = bk + h * 128;
    float s = 0.f;
#pragma unroll 8
    for (int d = 0; d < 128; d++) s += qr[d] * br[d];
    cvec[hq] = s * 0.08838834764831845f;   // 1/sqrt(128)
}

// bo2[f] = bo[f] + sum_g wo[f,g] * bv[g]   (one warp per f)
__global__ void bo2_kernel(const float* __restrict__ wo, const float* __restrict__ bv,
                           const float* __restrict__ bo, float* __restrict__ bo2)
{
    int gid  = blockIdx.x * blockDim.x + threadIdx.x;
    int f    = gid >> 5;
    int lane = gid & 31;
    if (f >= 2048) return;
    const float* wr = wo + (long long)f * 2048;
    float s = 0.f;
    for (int g = lane; g < 2048; g += 32) s += wr[g] * bv[g];
    s = warpSum(s);
    if (lane == 0) bo2[f] = bo[f] + s;
}

// ---------------------------------------------------------------------------
// Softmax over l for one (b,hq) row of S, with pe/bk add + mask.
// 128 threads, 8 l per thread. In-place.
// ---------------------------------------------------------------------------
__global__ void softmax_kernel(float* __restrict__ S, const float* __restrict__ P,
                               const float* __restrict__ cvec,
                               const int* __restrict__ tgt)
{
    __shared__ float sh[4];
    __shared__ float s_mx, s_inv;
    const int hq = blockIdx.x;
    const int b  = blockIdx.y;
    const int t  = threadIdx.x;

    int hh = tgt[2 * b];
    int ww = tgt[2 * b + 1];
    ww = min(max(ww, 1), 32);
    const int hw = hh * ww;

    float* row = S + ((long long)(b * 1024 + hq)) * 1024;
    const float* Pr = P + (long long)hq * 1024;
    const float cv  = cvec[hq];

    float vals[8];
    float mx = -3.4e38f;
#pragma unroll
    for (int i = 0; i < 8; i++) {
        int l = t + i * 128;
        float s;
        if (l < hw) {
            int r0 = l / ww;
            int cc = l - r0 * ww;
            int r  = r0 > 31 ? 31 : r0;
            s = row[l] + Pr[r * 32 + cc] + cv;
        } else {
            s = -1e9f;
        }
        vals[i] = s;
        mx = fmaxf(mx, s);
    }
    mx = warpMax(mx);
    if ((t & 31) == 0) sh[t >> 5] = mx;
    __syncthreads();
    if (t == 0) s_mx = fmaxf(fmaxf(sh[0], sh[1]), fmaxf(sh[2], sh[3]));
    __syncthreads();
    mx = s_mx;

    float sum = 0.f;
#pragma unroll
    for (int i = 0; i < 8; i++) {
        float e = expf(vals[i] - mx);
        vals[i] = e;
        sum += e;
    }
    sum = warpSum(sum);
    __syncthreads();
    if ((t & 31) == 0) sh[t >> 5] = sum;
    __syncthreads();
    if (t == 0) s_inv = 1.f / (sh[0] + sh[1] + sh[2] + sh[3]);
    __syncthreads();
    const float inv = s_inv;
#pragma unroll
    for (int i = 0; i < 8; i++) row[t + i * 128] = vals[i] * inv;
}

// ---------------------------------------------------------------------------
// Launch
// ---------------------------------------------------------------------------
extern "C" void kernel_launch(void* const* d_in, const int* in_sizes, int n_in,
                              void* d_out, int out_size)
{
    (void)in_sizes; (void)n_in; (void)out_size;
    const float* img       = (const float*)d_in[0];
    const int*   tgt       = (const int*)  d_in[1];
    const float* query     = (const float*)d_in[2];
    const float* kv_w      = (const float*)d_in[3];
    const float* ln_q_g    = (const float*)d_in[4];
    const float* ln_q_b    = (const float*)d_in[5];
    const float* ln_kv_g   = (const float*)d_in[6];
    const float* ln_kv_b   = (const float*)d_in[7];
    const float* ln_post_g = (const float*)d_in[8];
    const float* ln_post_b = (const float*)d_in[9];
    const float* wq        = (const float*)d_in[10];
    const float* bq        = (const float*)d_in[11];
    const float* wk        = (const float*)d_in[12];
    const float* bk        = (const float*)d_in[13];
    const float* wv        = (const float*)d_in[14];
    const float* bv        = (const float*)d_in[15];
    const float* wo        = (const float*)d_in[16];
    const float* bo        = (const float*)d_in[17];
    const float* proj      = (const float*)d_in[18];
    float* out = (float*)d_out;

    float *pX, *pS, *pT, *pA, *pP, *pPE, *pQln, *pQh, *pC, *pT2, *pO2, *pBo2;
    cudaGetSymbolAddress((void**)&pX,   g_X);
    cudaGetSymbolAddress((void**)&pS,   g_S);
    cudaGetSymbolAddress((void**)&pT,   g_T);
    cudaGetSymbolAddress((void**)&pA,   g_A);
    cudaGetSymbolAddress((void**)&pP,   g_P);
    cudaGetSymbolAddress((void**)&pPE,  g_pe);
    cudaGetSymbolAddress((void**)&pQln, g_qln);
    cudaGetSymbolAddress((void**)&pQh,  g_qh);
    cudaGetSymbolAddress((void**)&pC,   g_c);
    cudaGetSymbolAddress((void**)&pT2,  g_t2);
    cudaGetSymbolAddress((void**)&pO2,  g_o2);
    cudaGetSymbolAddress((void**)&pBo2, g_bo2);

    const float INV = 0.08838834764831845f;   // 1/sqrt(128)
    const long long LE  = (long long)C_L * C_E;      // 1024*2048
    const long long LHQ = (long long)C_HQ * C_L;     // 1024*1024

    // --- tiny prologue (query side, pe, bias folds) ---
    pe_kernel<<<1024, 256>>>(pPE);
    ln_kernel<<<64, 256>>>(query, pQln, ln_q_g, ln_q_b);
    // qh = qln @ wq^T + bq    (64 x 2048, K=2048)
    sgemm_kernel<64,128,32,8,8,1><<<dim3(16,1,1),128>>>(
        pQln, 2048, wq, 2048, pQh, 2048, 64, 2048, 2048, 1.f, bq,
        0,0, 0,0, 0,0, 1);
    // A[h*64+q, e] = (1/sqrt(DH)) sum_d qh[q, h*128+d] * wk[h*128+d, e]   (z = h)
    sgemm_kernel<64,128,32,8,8,0><<<dim3(16,1,16),128>>>(
        pQh, 2048, wk, 2048, pA, 2048, 64, 2048, 128, INV, nullptr,
        128,0, (long long)128*2048,0, (long long)64*2048,0, 1);
    c_kernel<<<8, 128>>>(pQh, bk, pC);
    bo2_kernel<<<256, 256>>>(wo, bv, bo, pBo2);
    // P[hq, pos] = A @ pe2d^T
    sgemm_kernel<128,128,32,8,8,1><<<dim3(8,8,1),256>>>(
        pA, 2048, pPE, 2048, pP, 1024, 1024, 1024, 2048, 1.f, nullptr,
        0,0, 0,0, 0,0, 1);

    // --- main pipeline ---
    // X = img @ kv_w^T   (32768 x 2048, K=1152)
    sgemm_kernel<128,128,32,8,8,1><<<dim3(16,256,1),256>>>(
        img, 1152, kv_w, 1152, pX, 2048, 32768, 2048, 1152, 1.f, nullptr,
        0,0, 0,0, 0,0, 1);
    // X = LN(X) in place
    ln_kernel<<<32768, 256>>>(pX, pX, ln_kv_g, ln_kv_b);
    // S[b][hq][l] = A @ X_b^T    (per batch, z = b)
    sgemm_kernel<128,128,32,8,8,1><<<dim3(8,8,32),256>>>(
        pA, 2048, pX, 2048, pS, 1024, 1024, 1024, 2048, 1.f, nullptr,
        0,0, LE,0, LHQ,0, 1);
    // softmax with pe/bk add + mask (in place on S)
    softmax_kernel<<<dim3(1024,32),128>>>(pS, pP, pC, tgt);
    // T[b][hq][e] = attn_b @ X_b   (per batch, z = b; NN, K = L)
    sgemm_kernel<128,128,32,8,8,0><<<dim3(16,8,32),256>>>(
        pS, 1024, pX, 2048, pT, 2048, 1024, 2048, 1024, 1.f, nullptr,
        LHQ,0, LE,0, LE,0, 1);
    // t2[b][q][h*128+d] = T[b][h*64+q] @ wv_h^T   (z = b*16+h, zmod=16)
    sgemm_kernel<64,128,32,8,8,1><<<dim3(1,1,512),128>>>(
        pT, 2048, wv, 2048, pT2, 2048, 64, 128, 2048, 1.f, nullptr,
        LE, (long long)64*2048,
        0,  (long long)128*2048,
        (long long)64*2048, 128, 16);
    // o2 = t2 @ wo^T + bo2   (2048 x 2048, K=2048)
    sgemm_kernel<128,128,32,8,8,1><<<dim3(16,16,1),256>>>(
        pT2, 2048, wo, 2048, pO2, 2048, 2048, 2048, 2048, 1.f, pBo2,
        0,0, 0,0, 0,0, 1);
    // o3 = LN(o2) in place
    ln_kernel<<<2048, 256>>>(pO2, pO2, ln_post_g, ln_post_b);
    // out = o3 @ proj   (NN, 2048 x 2048, K=2048)
    sgemm_kernel<128,128,32,8,8,0><<<dim3(16,16,1),256>>>(
        pO2, 2048, proj, 2048, out, 2048, 2048, 2048, 2048, 1.f, nullptr,
        0,0, 0,0, 0,0, 1);
}

// round 7
// speedup vs baseline: 1.8147x; 1.8147x over previous
#include <cuda_runtime.h>
#include <cuda_bf16.h>
#include <cstdint>

constexpr int C_E  = 2048;
constexpr int C_NQ = 64;
constexpr int C_B  = 32;
constexpr int C_L  = 1024;
constexpr int C_HQ = 1024;
constexpr long long LE  = (long long)C_L * C_E;
constexpr long long LHQ = (long long)C_HQ * C_L;

// fp32 scratch
__device__ float g_X  [(size_t)C_B * C_L * C_E];
__device__ float g_S  [(size_t)C_B * C_HQ * C_L];
__device__ float g_T  [(size_t)C_B * C_HQ * C_E];
__device__ float g_A  [(size_t)C_HQ * C_E];
__device__ float g_P  [(size_t)C_HQ * 1024];
__device__ float g_pe [(size_t)1024 * C_E];
__device__ float g_qln[(size_t)C_NQ * C_E];
__device__ float g_qh [(size_t)C_NQ * C_E];
__device__ float g_c  [C_HQ];
__device__ float g_t2 [(size_t)C_B * C_NQ * C_E];
__device__ float g_o2 [(size_t)C_B * C_NQ * C_E];
__device__ float g_bo2[C_E];
// bf16 split scratch
__device__ __nv_bfloat16 g_imgh[(size_t)C_B * C_L * 1152];
__device__ __nv_bfloat16 g_imgl[(size_t)C_B * C_L * 1152];
__device__ __nv_bfloat16 g_kwh [(size_t)C_E * 1152];
__device__ __nv_bfloat16 g_kwl [(size_t)C_E * 1152];
__device__ __nv_bfloat16 g_Xh  [(size_t)C_B * C_L * C_E];
__device__ __nv_bfloat16 g_Xl  [(size_t)C_B * C_L * C_E];
__device__ __nv_bfloat16 g_XTh [(size_t)C_B * C_E * C_L];
__device__ __nv_bfloat16 g_XTl [(size_t)C_B * C_E * C_L];
__device__ __nv_bfloat16 g_Sh  [(size_t)C_B * C_HQ * C_L];
__device__ __nv_bfloat16 g_Sl  [(size_t)C_B * C_HQ * C_L];
__device__ __nv_bfloat16 g_Ahh [(size_t)C_HQ * C_E];
__device__ __nv_bfloat16 g_Ahl [(size_t)C_HQ * C_E];
__device__ __nv_bfloat16 g_t2h [(size_t)C_B * C_NQ * C_E];
__device__ __nv_bfloat16 g_t2l [(size_t)C_B * C_NQ * C_E];
__device__ __nv_bfloat16 g_o3h [(size_t)C_B * C_NQ * C_E];
__device__ __nv_bfloat16 g_o3l [(size_t)C_B * C_NQ * C_E];
__device__ __nv_bfloat16 g_woh [(size_t)C_E * C_E];
__device__ __nv_bfloat16 g_wol [(size_t)C_E * C_E];
__device__ __nv_bfloat16 g_pjh [(size_t)C_E * C_E];
__device__ __nv_bfloat16 g_pjl [(size_t)C_E * C_E];

// ---------------- helpers ----------------
__device__ __forceinline__ uint32_t smem_u32(const void* p) {
    uint32_t a;
    asm("{ .reg .u64 t; cvta.to.shared.u64 t, %1; cvt.u32.u64 %0, t; }" : "=r"(a) : "l"(p));
    return a;
}
#define CP_ASYNC16(sa, gp) asm volatile("cp.async.cg.shared.global [%0], [%1], 16;" :: "r"(sa), "l"(gp))
#define CP_COMMIT()        asm volatile("cp.async.commit_group;" ::: "memory")
#define CP_WAIT1()         asm volatile("cp.async.wait_group 1;" ::: "memory")
#define CP_WAIT0()         asm volatile("cp.async.wait_group 0;" ::: "memory")

#define MMA16816(d, a, b) \
    asm volatile("mma.sync.aligned.m16n8k16.row.col.f32.bf16.bf16.f32 " \
        "{%0,%1,%2,%3}, {%4,%5,%6,%7}, {%8,%9}, {%0,%1,%2,%3};" \
        : "+f"((d)[0]), "+f"((d)[1]), "+f"((d)[2]), "+f"((d)[3]) \
        : "r"((a)[0]), "r"((a)[1]), "r"((a)[2]), "r"((a)[3]), "r"((b)[0]), "r"((b)[1]))

__device__ __forceinline__ void bsplit(float x, unsigned short& h, unsigned short& l) {
    __nv_bfloat16 hb = __float2bfloat16(x);
    __nv_bfloat16 lb = __float2bfloat16(x - __bfloat162float(hb));
    h = __bfloat16_as_ushort(hb); l = __bfloat16_as_ushort(lb);
}

// ---------------- split-bf16 NT GEMM via mma.sync (HMMA) ----------------
// C[m,n] = sum_k A[m,k]*B[n,k] (+bias[n]).  M,N multiples of 128, K of 32.
// 128x128 CTA tile, BK=32, double-buffered cp.async. 8 warps of 64x32.
constexpr int MG_ROW   = 40;              // 32 + 8 pad (bf16 elems per row)
constexpr int MG_TILE  = 128 * MG_ROW;    // 5120 elems per tile
constexpr int MG_SMEM  = 2 * 4 * MG_TILE * 2;  // bytes = 81920

__global__ void __launch_bounds__(256, 1)
mma_gemm(const __nv_bfloat16* __restrict__ Ah, const __nv_bfloat16* __restrict__ Al, int lda,
         const __nv_bfloat16* __restrict__ Bh, const __nv_bfloat16* __restrict__ Bl, int ldb,
         float* __restrict__ C, int ldc, int K, const float* __restrict__ bias,
         long long sA, long long sB, long long sC)
{
    extern __shared__ __nv_bfloat16 sm[];
    const uint32_t smb = smem_u32(sm);
    const int tid = threadIdx.x;
    const int wid = tid >> 5, lane = tid & 31;
    const long long z = blockIdx.z;
    Ah += z * sA; Al += z * sA; Bh += z * sB; Bl += z * sB; C += z * sC;
    const int m0 = blockIdx.y * 128, n0 = blockIdx.x * 128;
    const int wm = (wid >> 2) * 64;   // 0 / 64
    const int wn = (wid & 3) * 32;    // 0..96
    const int nsl = K >> 5;

    const __nv_bfloat16* srcs[4] = {Ah, Al, Bh, Bl};

    auto load_slab = [&](int buf, int k0) {
#pragma unroll
        for (int t = 0; t < 4; t++) {
            const __nv_bfloat16* s = srcs[t];
            const int rb = (t < 2) ? m0 : n0;
            const int ld = (t < 2) ? lda : ldb;
            const uint32_t base = (uint32_t)((buf * 4 + t) * MG_TILE);
#pragma unroll
            for (int it = 0; it < 2; it++) {
                int idx = tid + it * 256;          // 0..511
                int row = idx >> 2, c = idx & 3;
                const __nv_bfloat16* gp = s + (long long)(rb + row) * ld + k0 + c * 8;
                uint32_t sa = smb + (base + (uint32_t)(row * MG_ROW + c * 8)) * 2u;
                CP_ASYNC16(sa, gp);
            }
        }
    };

    float acc[4][4][4];
#pragma unroll
    for (int i = 0; i < 4; i++)
#pragma unroll
        for (int j = 0; j < 4; j++)
#pragma unroll
            for (int r = 0; r < 4; r++) acc[i][j][r] = 0.f;

    load_slab(0, 0); CP_COMMIT();

    for (int s = 0; s < nsl; s++) {
        if (s + 1 < nsl) { load_slab((s + 1) & 1, (s + 1) << 5); CP_COMMIT(); CP_WAIT1(); }
        else             { CP_WAIT0(); }
        __syncthreads();

        const int buf = s & 1;
        const __nv_bfloat16* ah_t = sm + (buf * 4 + 0) * MG_TILE;
        const __nv_bfloat16* al_t = sm + (buf * 4 + 1) * MG_TILE;
        const __nv_bfloat16* bh_t = sm + (buf * 4 + 2) * MG_TILE;
        const __nv_bfloat16* bl_t = sm + (buf * 4 + 3) * MG_TILE;

#pragma unroll
        for (int k16 = 0; k16 < 2; k16++) {
            const int kb = k16 * 16 + (lane & 3) * 2;
            uint32_t bh[4][2], bl[4][2];
#pragma unroll
            for (int j = 0; j < 4; j++) {
                int n = wn + j * 8 + (lane >> 2);
                bh[j][0] = *reinterpret_cast<const uint32_t*>(bh_t + n * MG_ROW + kb);
                bh[j][1] = *reinterpret_cast<const uint32_t*>(bh_t + n * MG_ROW + kb + 8);
                bl[j][0] = *reinterpret_cast<const uint32_t*>(bl_t + n * MG_ROW + kb);
                bl[j][1] = *reinterpret_cast<const uint32_t*>(bl_t + n * MG_ROW + kb + 8);
            }
#pragma unroll
            for (int i = 0; i < 4; i++) {
                int r = wm + i * 16 + (lane >> 2);
                uint32_t ah[4], al[4];
                ah[0] = *reinterpret_cast<const uint32_t*>(ah_t + r * MG_ROW + kb);
                ah[1] = *reinterpret_cast<const uint32_t*>(ah_t + (r + 8) * MG_ROW + kb);
                ah[2] = *reinterpret_cast<const uint32_t*>(ah_t + r * MG_ROW + kb + 8);
                ah[3] = *reinterpret_cast<const uint32_t*>(ah_t + (r + 8) * MG_ROW + kb + 8);
                al[0] = *reinterpret_cast<const uint32_t*>(al_t + r * MG_ROW + kb);
                al[1] = *reinterpret_cast<const uint32_t*>(al_t + (r + 8) * MG_ROW + kb);
                al[2] = *reinterpret_cast<const uint32_t*>(al_t + r * MG_ROW + kb + 8);
                al[3] = *reinterpret_cast<const uint32_t*>(al_t + (r + 8) * MG_ROW + kb + 8);
#pragma unroll
                for (int j = 0; j < 4; j++) {
                    MMA16816(acc[i][j], ah, bh[j]);
                    MMA16816(acc[i][j], ah, bl[j]);
                    MMA16816(acc[i][j], al, bh[j]);
                }
            }
        }
        __syncthreads();
    }

    // epilogue
#pragma unroll
    for (int i = 0; i < 4; i++) {
        int r = m0 + wm + i * 16 + (lane >> 2);
#pragma unroll
        for (int j = 0; j < 4; j++) {
            int cB = n0 + wn + j * 8 + (lane & 3) * 2;
            float b0 = bias ? bias[cB] : 0.f;
            float b1 = bias ? bias[cB + 1] : 0.f;
            float2 v0 = make_float2(acc[i][j][0] + b0, acc[i][j][1] + b1);
            float2 v1 = make_float2(acc[i][j][2] + b0, acc[i][j][3] + b1);
            *reinterpret_cast<float2*>(C + (long long)r * ldc + cB) = v0;
            *reinterpret_cast<float2*>(C + (long long)(r + 8) * ldc + cB) = v1;
        }
    }
}

// ---------------- warp reductions ----------------
__device__ __forceinline__ float warpSum(float v) {
#pragma unroll
    for (int o = 16; o > 0; o >>= 1) v += __shfl_xor_sync(0xffffffffu, v, o);
    return v;
}
__device__ __forceinline__ float warpMax(float v) {
#pragma unroll
    for (int o = 16; o > 0; o >>= 1) v = fmaxf(v, __shfl_xor_sync(0xffffffffu, v, o));
    return v;
}

// ---------------- SIMT SGEMM (small ops) ----------------
template<int BM, int BN, int BK, int TM, int TN, int TRANSB>
__global__ void __launch_bounds__((BM/TM)*(BN/TN))
sgemm_kernel(const float* __restrict__ Ag, int lda,
             const float* __restrict__ Bg, int ldb,
             float* __restrict__ Cg, int ldc,
             int M, int N, int K, float alpha, const float* __restrict__ bias,
             long long sAd, long long sAm, long long sBd, long long sBm,
             long long sCd, long long sCm, int zmod)
{
    constexpr int NTH = (BM/TM)*(BN/TN);
    constexpr int TCOLS = BN/TN;
    __shared__ float As[BK][BM+4];
    __shared__ float Bs[BK][BN+4];
    int z = blockIdx.z, zd = z / zmod, zm = z - zd*zmod;
    Ag += zd*sAd + zm*sAm; Bg += zd*sBd + zm*sBm; Cg += zd*sCd + zm*sCm;
    const int tid = threadIdx.x;
    const int m0 = blockIdx.y*BM, n0 = blockIdx.x*BN;
    const int tr = tid / TCOLS, tc = tid - tr*TCOLS;
    const int row0 = tr*TM, col0 = tc*TN;
    float acc[TM][TN];
#pragma unroll
    for (int i = 0; i < TM; i++)
#pragma unroll
        for (int j = 0; j < TN; j++) acc[i][j] = 0.f;
    for (int k0 = 0; k0 < K; k0 += BK) {
#pragma unroll
        for (int it = 0; it < BM*BK/4/NTH; it++) {
            int idx = tid + it*NTH;
            int r = idx/(BK/4), kk = (idx - r*(BK/4))*4;
            int gr = m0 + r; if (gr > M-1) gr = M-1;
            float4 v = *reinterpret_cast<const float4*>(Ag + (long long)gr*lda + k0 + kk);
            As[kk+0][r]=v.x; As[kk+1][r]=v.y; As[kk+2][r]=v.z; As[kk+3][r]=v.w;
        }
        if (TRANSB) {
#pragma unroll
            for (int it = 0; it < BN*BK/4/NTH; it++) {
                int idx = tid + it*NTH;
                int c = idx/(BK/4), kk = (idx - c*(BK/4))*4;
                int gc = n0 + c; if (gc > N-1) gc = N-1;
                float4 v = *reinterpret_cast<const float4*>(Bg + (long long)gc*ldb + k0 + kk);
                Bs[kk+0][c]=v.x; Bs[kk+1][c]=v.y; Bs[kk+2][c]=v.z; Bs[kk+3][c]=v.w;
            }
        } else {
#pragma unroll
            for (int it = 0; it < BK*BN/4/NTH; it++) {
                int idx = tid + it*NTH;
                int kk = idx/(BN/4), c4 = (idx - kk*(BN/4))*4;
                float4 v = *reinterpret_cast<const float4*>(Bg + (long long)(k0+kk)*ldb + n0 + c4);
                *reinterpret_cast<float4*>(&Bs[kk][c4]) = v;
            }
        }
        __syncthreads();
#pragma unroll
        for (int k = 0; k < BK; k++) {
            float ar[TM], br[TN];
#pragma unroll
            for (int i = 0; i < TM; i += 4) {
                float4 t = *reinterpret_cast<const float4*>(&As[k][row0+i]);
                ar[i]=t.x; ar[i+1]=t.y; ar[i+2]=t.z; ar[i+3]=t.w;
            }
#pragma unroll
            for (int j = 0; j < TN; j += 4) {
                float4 t = *reinterpret_cast<const float4*>(&Bs[k][col0+j]);
                br[j]=t.x; br[j+1]=t.y; br[j+2]=t.z; br[j+3]=t.w;
            }
#pragma unroll
            for (int i = 0; i < TM; i++)
#pragma unroll
                for (int j = 0; j < TN; j++)
                    acc[i][j] = fmaf(ar[i], br[j], acc[i][j]);
        }
        __syncthreads();
    }
#pragma unroll
    for (int i = 0; i < TM; i++) {
        int gr = m0 + row0 + i;
        if (gr < M) {
            float* cp = Cg + (long long)gr*ldc + n0 + col0;
#pragma unroll
            for (int j = 0; j < TN; j += 4) {
                int gc = n0 + col0 + j;
                float4 v;
                v.x = alpha*acc[i][j+0] + (bias ? bias[gc+0] : 0.f);
                v.y = alpha*acc[i][j+1] + (bias ? bias[gc+1] : 0.f);
                v.z = alpha*acc[i][j+2] + (bias ? bias[gc+2] : 0.f);
                v.w = alpha*acc[i][j+3] + (bias ? bias[gc+3] : 0.f);
                *reinterpret_cast<float4*>(cp + j) = v;
            }
        }
    }
}

// ---------------- LN (fp32 out) ----------------
__global__ void ln_kernel(const float* __restrict__ in, float* __restrict__ outp,
                          const float* __restrict__ gam, const float* __restrict__ bet)
{
    __shared__ float sh[8];
    __shared__ float s_mu, s_rs;
    const int row = blockIdx.x, t = threadIdx.x;
    const float* x = in + (long long)row*2048;
    float* y = outp + (long long)row*2048;
    float v[8]; float s = 0.f;
#pragma unroll
    for (int i = 0; i < 2; i++) {
        float4 f = *reinterpret_cast<const float4*>(x + (t + i*256)*4);
        v[i*4+0]=f.x; v[i*4+1]=f.y; v[i*4+2]=f.z; v[i*4+3]=f.w;
        s += f.x + f.y + f.z + f.w;
    }
    s = warpSum(s);
    if ((t&31)==0) sh[t>>5] = s;
    __syncthreads();
    if (t==0) { float tot=0.f;
#pragma unroll
        for (int i=0;i<8;i++) tot+=sh[i]; s_mu = tot*(1.f/2048.f); }
    __syncthreads();
    const float mu = s_mu;
    float q = 0.f;
#pragma unroll
    for (int i=0;i<8;i++){ float d=v[i]-mu; q+=d*d; }
    q = warpSum(q);
    __syncthreads();
    if ((t&31)==0) sh[t>>5] = q;
    __syncthreads();
    if (t==0) { float tot=0.f;
#pragma unroll
        for (int i=0;i<8;i++) tot+=sh[i]; s_rs = rsqrtf(tot*(1.f/2048.f)+1e-5f); }
    __syncthreads();
    const float rs = s_rs;
#pragma unroll
    for (int i=0;i<2;i++) {
        int idx = (t + i*256)*4;
        float4 g4 = *reinterpret_cast<const float4*>(gam+idx);
        float4 b4 = *reinterpret_cast<const float4*>(bet+idx);
        float4 o;
        o.x=(v[i*4+0]-mu)*rs*g4.x+b4.x; o.y=(v[i*4+1]-mu)*rs*g4.y+b4.y;
        o.z=(v[i*4+2]-mu)*rs*g4.z+b4.z; o.w=(v[i*4+3]-mu)*rs*g4.w+b4.w;
        *reinterpret_cast<float4*>(y+idx) = o;
    }
}

// LN -> bf16 hi/lo split (width 2048)
__global__ void ln_split_kernel(const float* __restrict__ in,
                                const float* __restrict__ gam, const float* __restrict__ bet,
                                __nv_bfloat16* __restrict__ hi, __nv_bfloat16* __restrict__ lo)
{
    __shared__ float sh[8];
    __shared__ float s_mu, s_rs;
    const int row = blockIdx.x, t = threadIdx.x;
    const float* x = in + (long long)row*2048;
    float v[8]; float s = 0.f;
#pragma unroll
    for (int i=0;i<2;i++) {
        float4 f = *reinterpret_cast<const float4*>(x + (t + i*256)*4);
        v[i*4+0]=f.x; v[i*4+1]=f.y; v[i*4+2]=f.z; v[i*4+3]=f.w;
        s += f.x + f.y + f.z + f.w;
    }
    s = warpSum(s);
    if ((t&31)==0) sh[t>>5]=s;
    __syncthreads();
    if (t==0){ float tot=0.f;
#pragma unroll
        for (int i=0;i<8;i++) tot+=sh[i]; s_mu=tot*(1.f/2048.f); }
    __syncthreads();
    const float mu=s_mu;
    float q=0.f;
#pragma unroll
    for (int i=0;i<8;i++){ float d=v[i]-mu; q+=d*d; }
    q=warpSum(q);
    __syncthreads();
    if ((t&31)==0) sh[t>>5]=q;
    __syncthreads();
    if (t==0){ float tot=0.f;
#pragma unroll
        for (int i=0;i<8;i++) tot+=sh[i]; s_rs=rsqrtf(tot*(1.f/2048.f)+1e-5f); }
    __syncthreads();
    const float rs=s_rs;
#pragma unroll
    for (int i=0;i<2;i++) {
        int idx = (t + i*256)*4;
        float4 g4 = *reinterpret_cast<const float4*>(gam+idx);
        float4 b4 = *reinterpret_cast<const float4*>(bet+idx);
        float o0=(v[i*4+0]-mu)*rs*g4.x+b4.x, o1=(v[i*4+1]-mu)*rs*g4.y+b4.y;
        float o2=(v[i*4+2]-mu)*rs*g4.z+b4.z, o3=(v[i*4+3]-mu)*rs*g4.w+b4.w;
        unsigned short h0,h1,h2,h3,l0,l1,l2,l3;
        bsplit(o0,h0,l0); bsplit(o1,h1,l1); bsplit(o2,h2,l2); bsplit(o3,h3,l3);
        uint2 hw, lw;
        hw.x=(uint32_t)h0|((uint32_t)h1<<16); hw.y=(uint32_t)h2|((uint32_t)h3<<16);
        lw.x=(uint32_t)l0|((uint32_t)l1<<16); lw.y=(uint32_t)l2|((uint32_t)l3<<16);
        *reinterpret_cast<uint2*>(hi + (long long)row*2048 + idx) = hw;
        *reinterpret_cast<uint2*>(lo + (long long)row*2048 + idx) = lw;
    }
}

// flat fp32 -> bf16 hi/lo
__global__ void split_kernel(const float* __restrict__ in,
                             __nv_bfloat16* __restrict__ hi, __nv_bfloat16* __restrict__ lo,
                             long long n4)
{
    long long i = (long long)blockIdx.x*blockDim.x + threadIdx.x;
    if (i >= n4) return;
    float4 v = reinterpret_cast<const float4*>(in)[i];
    unsigned short h0,h1,h2,h3,l0,l1,l2,l3;
    bsplit(v.x,h0,l0); bsplit(v.y,h1,l1); bsplit(v.z,h2,l2); bsplit(v.w,h3,l3);
    uint2 hw, lw;
    hw.x=(uint32_t)h0|((uint32_t)h1<<16); hw.y=(uint32_t)h2|((uint32_t)h3<<16);
    lw.x=(uint32_t)l0|((uint32_t)l1<<16); lw.y=(uint32_t)l2|((uint32_t)l3<<16);
    reinterpret_cast<uint2*>(hi)[i] = hw;
    reinterpret_cast<uint2*>(lo)[i] = lw;
}

// batched bf16 pair transpose: [R x C] -> [C x R]
__global__ void tbf16_kernel(const __nv_bfloat16* __restrict__ ih, const __nv_bfloat16* __restrict__ il,
                             __nv_bfloat16* __restrict__ oh, __nv_bfloat16* __restrict__ ol,
                             int R, int C, long long sS, long long sD)
{
    __shared__ __nv_bfloat16 th[32][33];
    __shared__ __nv_bfloat16 tl[32][33];
    long long zs = (long long)blockIdx.z*sS, zd = (long long)blockIdx.z*sD;
    int x0 = blockIdx.x*32, y0 = blockIdx.y*32;
    int tx = threadIdx.x, ty = threadIdx.y;
#pragma unroll
    for (int j = 0; j < 32; j += 8) {
        long long src = zs + (long long)(y0+ty+j)*C + x0 + tx;
        th[ty+j][tx] = ih[src]; tl[ty+j][tx] = il[src];
    }
    __syncthreads();
#pragma unroll
    for (int j = 0; j < 32; j += 8) {
        long long dst = zd + (long long)(x0+ty+j)*R + y0 + tx;
        oh[dst] = th[tx][ty+j]; ol[dst] = tl[tx][ty+j];
    }
}

// fp32 [R x C] -> transposed bf16 hi/lo [C x R]
__global__ void tsplit32_kernel(const float* __restrict__ in,
                                __nv_bfloat16* __restrict__ hi, __nv_bfloat16* __restrict__ lo,
                                int R, int C)
{
    __shared__ float tile[32][33];
    int x0 = blockIdx.x*32, y0 = blockIdx.y*32;
    int tx = threadIdx.x, ty = threadIdx.y;
#pragma unroll
    for (int j = 0; j < 32; j += 8)
        tile[ty+j][tx] = in[(long long)(y0+ty+j)*C + x0 + tx];
    __syncthreads();
#pragma unroll
    for (int j = 0; j < 32; j += 8) {
        float v = tile[tx][ty+j];
        unsigned short h, l;
        bsplit(v, h, l);
        long long dst = (long long)(x0+ty+j)*R + y0 + tx;
        hi[dst] = __ushort_as_bfloat16(h);
        lo[dst] = __ushort_as_bfloat16(l);
    }
}

// ---------------- pe / folds / softmax ----------------
__global__ void pe_kernel(float* __restrict__ pe)
{
    const int pos = blockIdx.x, r = pos>>5, cc = pos&31, t = threadIdx.x;
    const float k = -9.210340371976184f / 512.f;
#pragma unroll
    for (int i=0;i<8;i++) {
        int e = t + i*256;
        int p = (e < 1024) ? r : cc;
        int ee = e & 1023;
        float val;
        if (ee < 512) val = sinf((float)p * expf((float)ee*k));
        else          val = cosf((float)p * expf((float)(ee-512)*k));
        pe[(long long)pos*2048 + e] = val;
    }
}

__global__ void c_kernel(const float* __restrict__ qh, const float* __restrict__ bk,
                         float* __restrict__ cvec)
{
    int hq = blockIdx.x*blockDim.x + threadIdx.x;
    if (hq >= 1024) return;
    int h = hq>>6, q = hq&63;
    const float* qr = qh + (long long)q*2048 + h*128;
    const float* br = bk + h*128;
    float s = 0.f;
#pragma unroll 8
    for (int d = 0; d < 128; d++) s += qr[d]*br[d];
    cvec[hq] = s * 0.08838834764831845f;
}

__global__ void bo2_kernel(const float* __restrict__ wo, const float* __restrict__ bv,
                           const float* __restrict__ bo, float* __restrict__ bo2)
{
    int gid = blockIdx.x*blockDim.x + threadIdx.x;
    int f = gid>>5, lane = gid&31;
    if (f >= 2048) return;
    const float* wr = wo + (long long)f*2048;
    float s = 0.f;
    for (int g = lane; g < 2048; g += 32) s += wr[g]*bv[g];
    s = warpSum(s);
    if (lane == 0) bo2[f] = bo[f] + s;
}

__global__ void softmax_split_kernel(const float* __restrict__ S, const float* __restrict__ P,
                                     const float* __restrict__ cvec, const int* __restrict__ tgt,
                                     __nv_bfloat16* __restrict__ Sh, __nv_bfloat16* __restrict__ Sl)
{
    __shared__ float sh[4];
    __shared__ float s_mx, s_inv;
    const int hq = blockIdx.x, b = blockIdx.y, t = threadIdx.x;
    int hh = tgt[2*b];
    int ww = tgt[2*b+1]; ww = min(max(ww,1),32);
    const int hw = hh*ww;
    const long long ro = (long long)(b*1024 + hq)*1024;
    const float* row = S + ro;
    const float* Pr = P + (long long)hq*1024;
    const float cv = cvec[hq];
    float vals[8]; float mx = -3.4e38f;
#pragma unroll
    for (int i = 0; i < 8; i++) {
        int l = t + i*128;
        float s;
        if (l < hw) {
            int r0 = l/ww, cc = l - r0*ww;
            int r = r0 > 31 ? 31 : r0;
            s = row[l] + Pr[r*32+cc] + cv;
        } else s = -1e9f;
        vals[i] = s; mx = fmaxf(mx, s);
    }
    mx = warpMax(mx);
    if ((t&31)==0) sh[t>>5]=mx;
    __syncthreads();
    if (t==0) s_mx = fmaxf(fmaxf(sh[0],sh[1]),fmaxf(sh[2],sh[3]));
    __syncthreads();
    mx = s_mx;
    float sum = 0.f;
#pragma unroll
    for (int i = 0; i < 8; i++) { float e = expf(vals[i]-mx); vals[i] = e; sum += e; }
    sum = warpSum(sum);
    __syncthreads();
    if ((t&31)==0) sh[t>>5]=sum;
    __syncthreads();
    if (t==0) s_inv = 1.f/(sh[0]+sh[1]+sh[2]+sh[3]);
    __syncthreads();
    const float inv = s_inv;
#pragma unroll
    for (int i = 0; i < 8; i++) {
        int l = t + i*128;
        unsigned short h, lo;
        bsplit(vals[i]*inv, h, lo);
        Sh[ro+l] = __ushort_as_bfloat16(h);
        Sl[ro+l] = __ushort_as_bfloat16(lo);
    }
}

// ---------------- launch ----------------
extern "C" void kernel_launch(void* const* d_in, const int* in_sizes, int n_in,
                              void* d_out, int out_size)
{
    (void)in_sizes; (void)n_in; (void)out_size;
    const float* img       = (const float*)d_in[0];
    const int*   tgt       = (const int*)  d_in[1];
    const float* query     = (const float*)d_in[2];
    const float* kv_w      = (const float*)d_in[3];
    const float* ln_q_g    = (const float*)d_in[4];
    const float* ln_q_b    = (const float*)d_in[5];
    const float* ln_kv_g   = (const float*)d_in[6];
    const float* ln_kv_b   = (const float*)d_in[7];
    const float* ln_post_g = (const float*)d_in[8];
    const float* ln_post_b = (const float*)d_in[9];
    const float* wq        = (const float*)d_in[10];
    const float* bq        = (const float*)d_in[11];
    const float* wk        = (const float*)d_in[12];
    const float* bk        = (const float*)d_in[13];
    const float* wv        = (const float*)d_in[14];
    const float* bv        = (const float*)d_in[15];
    const float* wo        = (const float*)d_in[16];
    const float* bo        = (const float*)d_in[17];
    const float* proj      = (const float*)d_in[18];
    float* out = (float*)d_out;

    float *pX,*pS,*pT,*pA,*pP,*pPE,*pQln,*pQh,*pC,*pT2,*pO2,*pBo2;
    __nv_bfloat16 *pImgh,*pImgl,*pKwh,*pKwl,*pXh,*pXl,*pXTh,*pXTl,*pSh,*pSl,*pAhh,*pAhl;
    __nv_bfloat16 *pT2h,*pT2l,*pO3h,*pO3l,*pWoh,*pWol,*pPjh,*pPjl;
    cudaGetSymbolAddress((void**)&pX, g_X);   cudaGetSymbolAddress((void**)&pS, g_S);
    cudaGetSymbolAddress((void**)&pT, g_T);   cudaGetSymbolAddress((void**)&pA, g_A);
    cudaGetSymbolAddress((void**)&pP, g_P);   cudaGetSymbolAddress((void**)&pPE, g_pe);
    cudaGetSymbolAddress((void**)&pQln, g_qln); cudaGetSymbolAddress((void**)&pQh, g_qh);
    cudaGetSymbolAddress((void**)&pC, g_c);   cudaGetSymbolAddress((void**)&pT2, g_t2);
    cudaGetSymbolAddress((void**)&pO2, g_o2); cudaGetSymbolAddress((void**)&pBo2, g_bo2);
    cudaGetSymbolAddress((void**)&pImgh, g_imgh); cudaGetSymbolAddress((void**)&pImgl, g_imgl);
    cudaGetSymbolAddress((void**)&pKwh, g_kwh);   cudaGetSymbolAddress((void**)&pKwl, g_kwl);
    cudaGetSymbolAddress((void**)&pXh, g_Xh);     cudaGetSymbolAddress((void**)&pXl, g_Xl);
    cudaGetSymbolAddress((void**)&pXTh, g_XTh);   cudaGetSymbolAddress((void**)&pXTl, g_XTl);
    cudaGetSymbolAddress((void**)&pSh, g_Sh);     cudaGetSymbolAddress((void**)&pSl, g_Sl);
    cudaGetSymbolAddress((void**)&pAhh, g_Ahh);   cudaGetSymbolAddress((void**)&pAhl, g_Ahl);
    cudaGetSymbolAddress((void**)&pT2h, g_t2h);   cudaGetSymbolAddress((void**)&pT2l, g_t2l);
    cudaGetSymbolAddress((void**)&pO3h, g_o3h);   cudaGetSymbolAddress((void**)&pO3l, g_o3l);
    cudaGetSymbolAddress((void**)&pWoh, g_woh);   cudaGetSymbolAddress((void**)&pWol, g_wol);
    cudaGetSymbolAddress((void**)&pPjh, g_pjh);   cudaGetSymbolAddress((void**)&pPjl, g_pjl);

    cudaFuncSetAttribute(mma_gemm, cudaFuncAttributeMaxDynamicSharedMemorySize, MG_SMEM);

    const float INV = 0.08838834764831845f;

    // prologue (query side, pe, folds) — SIMT, small
    pe_kernel<<<1024, 256>>>(pPE);
    ln_kernel<<<64, 256>>>(query, pQln, ln_q_g, ln_q_b);
    sgemm_kernel<64,128,32,8,8,1><<<dim3(16,1,1),128>>>(
        pQln, 2048, wq, 2048, pQh, 2048, 64, 2048, 2048, 1.f, bq, 0,0,0,0,0,0, 1);
    sgemm_kernel<64,128,32,8,8,0><<<dim3(16,1,16),128>>>(
        pQh, 2048, wk, 2048, pA, 2048, 64, 2048, 128, INV, nullptr,
        128,0, (long long)128*2048,0, (long long)64*2048,0, 1);
    c_kernel<<<8,128>>>(pQh, bk, pC);
    bo2_kernel<<<256,256>>>(wo, bv, bo, pBo2);
    sgemm_kernel<128,128,32,8,8,1><<<dim3(8,8,1),256>>>(
        pA, 2048, pPE, 2048, pP, 1024, 1024, 1024, 2048, 1.f, nullptr, 0,0,0,0,0,0, 1);
    split_kernel<<<2048, 256>>>(pA, pAhh, pAhl, (long long)C_HQ*C_E/4);

    // splits for tensor GEMMs
    split_kernel<<<36864, 256>>>(img, pImgh, pImgl, (long long)C_B*C_L*1152/4);
    split_kernel<<<2304, 256>>>(kv_w, pKwh, pKwl, (long long)C_E*1152/4);
    split_kernel<<<4096, 256>>>(wo, pWoh, pWol, (long long)C_E*C_E/4);
    tsplit32_kernel<<<dim3(64,64), dim3(32,8)>>>(proj, pPjh, pPjl, 2048, 2048);

    // X = img @ kv_w^T  [32768 x 2048], K=1152
    mma_gemm<<<dim3(16,256,1), 256, MG_SMEM>>>(
        pImgh, pImgl, 1152, pKwh, pKwl, 1152, pX, 2048, 1152, nullptr, 0,0,0);
    // LN(X) -> bf16 split
    ln_split_kernel<<<32768, 256>>>(pX, ln_kv_g, ln_kv_b, pXh, pXl);
    // XT per batch [e][l]
    tbf16_kernel<<<dim3(64,32,32), dim3(32,8)>>>(pXh, pXl, pXTh, pXTl, 1024, 2048, LE, LE);

    // S[b] = A @ X_b^T  per batch
    mma_gemm<<<dim3(8,8,32), 256, MG_SMEM>>>(
        pAhh, pAhl, 2048, pXh, pXl, 2048, pS, 1024, 2048, nullptr, 0, LE, LHQ);
    // softmax (+pe/bk/mask) -> bf16 split
    softmax_split_kernel<<<dim3(1024,32),128>>>(pS, pP, pC, tgt, pSh, pSl);
    // T[b] = attn_b @ X_b  (NT via XT)
    mma_gemm<<<dim3(16,8,32), 256, MG_SMEM>>>(
        pSh, pSl, 1024, pXTh, pXTl, 1024, pT, 2048, 1024, nullptr, LHQ, LE, LE);

    // per-head V projection (SIMT): t2[b][q] = T[b][h*64+q] @ wv_h^T
    sgemm_kernel<64,128,32,8,8,1><<<dim3(1,1,512),128>>>(
        pT, 2048, wv, 2048, pT2, 2048, 64, 128, 2048, 1.f, nullptr,
        LE, (long long)64*2048, 0, (long long)128*2048, (long long)64*2048, 128, 16);
    // o2 = t2 @ wo^T + bo2
    split_kernel<<<4096, 256>>>(pT2, pT2h, pT2l, (long long)C_B*C_NQ*C_E/4);
    mma_gemm<<<dim3(16,16,1), 256, MG_SMEM>>>(
        pT2h, pT2l, 2048, pWoh, pWol, 2048, pO2, 2048, 2048, pBo2, 0,0,0);
    // LN(o2) -> bf16 split
    ln_split_kernel<<<2048, 256>>>(pO2, ln_post_g, ln_post_b, pO3h, pO3l);
    // out = o3 @ proj  (NT via projT)
    mma_gemm<<<dim3(16,16,1), 256, MG_SMEM>>>(
        pO3h, pO3l, 2048, pPjh, pPjl, 2048, out, 2048, 2048, nullptr, 0,0,0);
}

// round 8
// speedup vs baseline: 2.1941x; 1.2090x over previous
#include <cuda_runtime.h>
#include <cuda_bf16.h>
#include <cstdint>

constexpr int C_E  = 2048;
constexpr int C_NQ = 64;
constexpr int C_B  = 32;
constexpr int C_L  = 1024;
constexpr int C_HQ = 1024;
constexpr long long LE  = (long long)C_L * C_E;
constexpr long long LHQ = (long long)C_HQ * C_L;

// fp32 scratch
__device__ float g_X  [(size_t)C_B * C_L * C_E];
__device__ float g_S  [(size_t)C_B * C_HQ * C_L];
__device__ float g_T  [(size_t)C_B * C_HQ * C_E];
__device__ float g_A  [(size_t)C_HQ * C_E];
__device__ float g_P  [(size_t)C_HQ * 1024];
__device__ float g_pe [(size_t)1024 * C_E];
__device__ float g_qln[(size_t)C_NQ * C_E];
__device__ float g_qh [(size_t)C_NQ * C_E];
__device__ float g_c  [C_HQ];
__device__ float g_t2 [(size_t)C_B * C_NQ * C_E];
__device__ float g_o2 [(size_t)C_B * C_NQ * C_E];
__device__ float g_bo2[C_E];
// bf16 split scratch
__device__ __nv_bfloat16 g_imgh[(size_t)C_B * C_L * 1152];
__device__ __nv_bfloat16 g_imgl[(size_t)C_B * C_L * 1152];
__device__ __nv_bfloat16 g_kwh [(size_t)C_E * 1152];
__device__ __nv_bfloat16 g_kwl [(size_t)C_E * 1152];
__device__ __nv_bfloat16 g_Xh  [(size_t)C_B * C_L * C_E];
__device__ __nv_bfloat16 g_Xl  [(size_t)C_B * C_L * C_E];
__device__ __nv_bfloat16 g_XTh [(size_t)C_B * C_E * C_L];
__device__ __nv_bfloat16 g_XTl [(size_t)C_B * C_E * C_L];
__device__ __nv_bfloat16 g_Sh  [(size_t)C_B * C_HQ * C_L];
__device__ __nv_bfloat16 g_Sl  [(size_t)C_B * C_HQ * C_L];
__device__ __nv_bfloat16 g_Ahh [(size_t)C_HQ * C_E];
__device__ __nv_bfloat16 g_Ahl [(size_t)C_HQ * C_E];
__device__ __nv_bfloat16 g_t2h [(size_t)C_B * C_NQ * C_E];
__device__ __nv_bfloat16 g_t2l [(size_t)C_B * C_NQ * C_E];
__device__ __nv_bfloat16 g_o3h [(size_t)C_B * C_NQ * C_E];
__device__ __nv_bfloat16 g_o3l [(size_t)C_B * C_NQ * C_E];
__device__ __nv_bfloat16 g_woh [(size_t)C_E * C_E];
__device__ __nv_bfloat16 g_wol [(size_t)C_E * C_E];
__device__ __nv_bfloat16 g_pjh [(size_t)C_E * C_E];
__device__ __nv_bfloat16 g_pjl [(size_t)C_E * C_E];

// ---------------- helpers ----------------
__device__ __forceinline__ uint32_t smem_u32(const void* p) {
    uint32_t a;
    asm("{ .reg .u64 t; cvta.to.shared.u64 t, %1; cvt.u32.u64 %0, t; }" : "=r"(a) : "l"(p));
    return a;
}
#define CP_ASYNC16(sa, gp) asm volatile("cp.async.cg.shared.global [%0], [%1], 16;" :: "r"(sa), "l"(gp))
#define CP_COMMIT()        asm volatile("cp.async.commit_group;" ::: "memory")
#define CP_WAIT1()         asm volatile("cp.async.wait_group 1;" ::: "memory")
#define CP_WAIT0()         asm volatile("cp.async.wait_group 0;" ::: "memory")

#define MMA16816(d, a, b) \
    asm volatile("mma.sync.aligned.m16n8k16.row.col.f32.bf16.bf16.f32 " \
        "{%0,%1,%2,%3}, {%4,%5,%6,%7}, {%8,%9}, {%0,%1,%2,%3};" \
        : "+f"((d)[0]), "+f"((d)[1]), "+f"((d)[2]), "+f"((d)[3]) \
        : "r"((a)[0]), "r"((a)[1]), "r"((a)[2]), "r"((a)[3]), "r"((b)[0]), "r"((b)[1]))

#define LDSM_X4(r0, r1, r2, r3, addr) \
    asm volatile("ldmatrix.sync.aligned.m8n8.x4.shared.b16 {%0,%1,%2,%3}, [%4];" \
        : "=r"(r0), "=r"(r1), "=r"(r2), "=r"(r3) : "r"(addr))

__device__ __forceinline__ void bsplit(float x, unsigned short& h, unsigned short& l) {
    __nv_bfloat16 hb = __float2bfloat16(x);
    __nv_bfloat16 lb = __float2bfloat16(x - __bfloat162float(hb));
    h = __bfloat16_as_ushort(hb); l = __bfloat16_as_ushort(lb);
}

// ---------------- split-bf16 NT GEMM via mma.sync + ldmatrix ----------------
// C[m,n] = sum_k A[m,k]*B[n,k] (+bias[n]).  M,N multiples of 128, K of 32.
// 128x128 CTA tile, BK=32, double-buffered cp.async. 8 warps of 64x32. 2 CTA/SM.
constexpr int MG_ROW   = 40;              // 32 + 8 pad (bf16 elems per row)
constexpr int MG_TILE  = 128 * MG_ROW;    // 5120 elems per tile
constexpr int MG_SMEM  = 2 * 4 * MG_TILE * 2;  // bytes = 81920

__global__ void __launch_bounds__(256, 2)
mma_gemm(const __nv_bfloat16* __restrict__ Ah, const __nv_bfloat16* __restrict__ Al, int lda,
         const __nv_bfloat16* __restrict__ Bh, const __nv_bfloat16* __restrict__ Bl, int ldb,
         float* __restrict__ C, int ldc, int K, const float* __restrict__ bias,
         long long sA, long long sB, long long sC)
{
    extern __shared__ __nv_bfloat16 sm[];
    const uint32_t smb = smem_u32(sm);
    const int tid = threadIdx.x;
    const int wid = tid >> 5, lane = tid & 31;
    const long long z = blockIdx.z;
    Ah += z * sA; Al += z * sA; Bh += z * sB; Bl += z * sB; C += z * sC;
    const int m0 = blockIdx.y * 128, n0 = blockIdx.x * 128;
    const int wm = (wid >> 2) * 64;   // 0 / 64
    const int wn = (wid & 3) * 32;    // 0..96
    const int nsl = K >> 5;

    const __nv_bfloat16* srcs[4] = {Ah, Al, Bh, Bl};

    auto load_slab = [&](int buf, int k0) {
#pragma unroll
        for (int t = 0; t < 4; t++) {
            const __nv_bfloat16* s = srcs[t];
            const int rb = (t < 2) ? m0 : n0;
            const int ld = (t < 2) ? lda : ldb;
            const uint32_t base = (uint32_t)((buf * 4 + t) * MG_TILE);
#pragma unroll
            for (int it = 0; it < 2; it++) {
                int idx = tid + it * 256;          // 0..511
                int row = idx >> 2, c = idx & 3;
                const __nv_bfloat16* gp = s + (long long)(rb + row) * ld + k0 + c * 8;
                uint32_t sa = smb + (base + (uint32_t)(row * MG_ROW + c * 8)) * 2u;
                CP_ASYNC16(sa, gp);
            }
        }
    };

    // ldmatrix lane address components (element offsets within a tile)
    const uint32_t aRow = (uint32_t)(((lane >> 3) & 1) * 8 + (lane & 7));  // + wm + i*16
    const uint32_t aCol = (uint32_t)((lane >> 4) * 8);                     // + k16*16
    const uint32_t bRow = (uint32_t)((lane >> 4) * 8 + (lane & 7));        // + wn + jg*16
    const uint32_t bCol = (uint32_t)(((lane >> 3) & 1) * 8);               // + k16*16

    float acc[4][4][4];
#pragma unroll
    for (int i = 0; i < 4; i++)
#pragma unroll
        for (int j = 0; j < 4; j++)
#pragma unroll
            for (int r = 0; r < 4; r++) acc[i][j][r] = 0.f;

    load_slab(0, 0); CP_COMMIT();

    for (int s = 0; s < nsl; s++) {
        if (s + 1 < nsl) { load_slab((s + 1) & 1, (s + 1) << 5); CP_COMMIT(); CP_WAIT1(); }
        else             { CP_WAIT0(); }
        __syncthreads();

        const int buf = s & 1;
        const uint32_t ah_b = smb + (uint32_t)(buf * 4 + 0) * MG_TILE * 2u;
        const uint32_t al_b = smb + (uint32_t)(buf * 4 + 1) * MG_TILE * 2u;
        const uint32_t bh_b = smb + (uint32_t)(buf * 4 + 2) * MG_TILE * 2u;
        const uint32_t bl_b = smb + (uint32_t)(buf * 4 + 3) * MG_TILE * 2u;

#pragma unroll
        for (int k16 = 0; k16 < 2; k16++) {
            const uint32_t kc = (uint32_t)(k16 * 16);
            uint32_t bh[4][2], bl[4][2];
#pragma unroll
            for (int jg = 0; jg < 2; jg++) {
                uint32_t off = ((uint32_t)(wn + jg * 16) + bRow) * MG_ROW + kc + bCol;
                LDSM_X4(bh[jg*2][0], bh[jg*2][1], bh[jg*2+1][0], bh[jg*2+1][1], bh_b + off * 2u);
                LDSM_X4(bl[jg*2][0], bl[jg*2][1], bl[jg*2+1][0], bl[jg*2+1][1], bl_b + off * 2u);
            }
#pragma unroll
            for (int i = 0; i < 4; i++) {
                uint32_t off = ((uint32_t)(wm + i * 16) + aRow) * MG_ROW + kc + aCol;
                uint32_t ah[4], al[4];
                LDSM_X4(ah[0], ah[1], ah[2], ah[3], ah_b + off * 2u);
                LDSM_X4(al[0], al[1], al[2], al[3], al_b + off * 2u);
#pragma unroll
                for (int j = 0; j < 4; j++) {
                    MMA16816(acc[i][j], ah, bh[j]);
                    MMA16816(acc[i][j], ah, bl[j]);
                    MMA16816(acc[i][j], al, bh[j]);
                }
            }
        }
        __syncthreads();
    }

    // epilogue
#pragma unroll
    for (int i = 0; i < 4; i++) {
        int r = m0 + wm + i * 16 + (lane >> 2);
#pragma unroll
        for (int j = 0; j < 4; j++) {
            int cB = n0 + wn + j * 8 + (lane & 3) * 2;
            float b0 = bias ? bias[cB] : 0.f;
            float b1 = bias ? bias[cB + 1] : 0.f;
            float2 v0 = make_float2(acc[i][j][0] + b0, acc[i][j][1] + b1);
            float2 v1 = make_float2(acc[i][j][2] + b0, acc[i][j][3] + b1);
            *reinterpret_cast<float2*>(C + (long long)r * ldc + cB) = v0;
            *reinterpret_cast<float2*>(C + (long long)(r + 8) * ldc + cB) = v1;
        }
    }
}

// ---------------- warp reductions ----------------
__device__ __forceinline__ float warpSum(float v) {
#pragma unroll
    for (int o = 16; o > 0; o >>= 1) v += __shfl_xor_sync(0xffffffffu, v, o);
    return v;
}
__device__ __forceinline__ float warpMax(float v) {
#pragma unroll
    for (int o = 16; o > 0; o >>= 1) v = fmaxf(v, __shfl_xor_sync(0xffffffffu, v, o));
    return v;
}

// ---------------- SIMT SGEMM (small ops) ----------------
template<int BM, int BN, int BK, int TM, int TN, int TRANSB>
__global__ void __launch_bounds__((BM/TM)*(BN/TN))
sgemm_kernel(const float* __restrict__ Ag, int lda,
             const float* __restrict__ Bg, int ldb,
             float* __restrict__ Cg, int ldc,
             int M, int N, int K, float alpha, const float* __restrict__ bias,
             long long sAd, long long sAm, long long sBd, long long sBm,
             long long sCd, long long sCm, int zmod)
{
    constexpr int NTH = (BM/TM)*(BN/TN);
    constexpr int TCOLS = BN/TN;
    __shared__ float As[BK][BM+4];
    __shared__ float Bs[BK][BN+4];
    int z = blockIdx.z, zd = z / zmod, zm = z - zd*zmod;
    Ag += zd*sAd + zm*sAm; Bg += zd*sBd + zm*sBm; Cg += zd*sCd + zm*sCm;
    const int tid = threadIdx.x;
    const int m0 = blockIdx.y*BM, n0 = blockIdx.x*BN;
    const int tr = tid / TCOLS, tc = tid - tr*TCOLS;
    const int row0 = tr*TM, col0 = tc*TN;
    float acc[TM][TN];
#pragma unroll
    for (int i = 0; i < TM; i++)
#pragma unroll
        for (int j = 0; j < TN; j++) acc[i][j] = 0.f;
    for (int k0 = 0; k0 < K; k0 += BK) {
#pragma unroll
        for (int it = 0; it < BM*BK/4/NTH; it++) {
            int idx = tid + it*NTH;
            int r = idx/(BK/4), kk = (idx - r*(BK/4))*4;
            int gr = m0 + r; if (gr > M-1) gr = M-1;
            float4 v = *reinterpret_cast<const float4*>(Ag + (long long)gr*lda + k0 + kk);
            As[kk+0][r]=v.x; As[kk+1][r]=v.y; As[kk+2][r]=v.z; As[kk+3][r]=v.w;
        }
        if (TRANSB) {
#pragma unroll
            for (int it = 0; it < BN*BK/4/NTH; it++) {
                int idx = tid + it*NTH;
                int c = idx/(BK/4), kk = (idx - c*(BK/4))*4;
                int gc = n0 + c; if (gc > N-1) gc = N-1;
                float4 v = *reinterpret_cast<const float4*>(Bg + (long long)gc*ldb + k0 + kk);
                Bs[kk+0][c]=v.x; Bs[kk+1][c]=v.y; Bs[kk+2][c]=v.z; Bs[kk+3][c]=v.w;
            }
        } else {
#pragma unroll
            for (int it = 0; it < BK*BN/4/NTH; it++) {
                int idx = tid + it*NTH;
                int kk = idx/(BN/4), c4 = (idx - kk*(BN/4))*4;
                float4 v = *reinterpret_cast<const float4*>(Bg + (long long)(k0+kk)*ldb + n0 + c4);
                *reinterpret_cast<float4*>(&Bs[kk][c4]) = v;
            }
        }
        __syncthreads();
#pragma unroll
        for (int k = 0; k < BK; k++) {
            float ar[TM], br[TN];
#pragma unroll
            for (int i = 0; i < TM; i += 4) {
                float4 t = *reinterpret_cast<const float4*>(&As[k][row0+i]);
                ar[i]=t.x; ar[i+1]=t.y; ar[i+2]=t.z; ar[i+3]=t.w;
            }
#pragma unroll
            for (int j = 0; j < TN; j += 4) {
                float4 t = *reinterpret_cast<const float4*>(&Bs[k][col0+j]);
                br[j]=t.x; br[j+1]=t.y; br[j+2]=t.z; br[j+3]=t.w;
            }
#pragma unroll
            for (int i = 0; i < TM; i++)
#pragma unroll
                for (int j = 0; j < TN; j++)
                    acc[i][j] = fmaf(ar[i], br[j], acc[i][j]);
        }
        __syncthreads();
    }
#pragma unroll
    for (int i = 0; i < TM; i++) {
        int gr = m0 + row0 + i;
        if (gr < M) {
            float* cp = Cg + (long long)gr*ldc + n0 + col0;
#pragma unroll
            for (int j = 0; j < TN; j += 4) {
                int gc = n0 + col0 + j;
                float4 v;
                v.x = alpha*acc[i][j+0] + (bias ? bias[gc+0] : 0.f);
                v.y = alpha*acc[i][j+1] + (bias ? bias[gc+1] : 0.f);
                v.z = alpha*acc[i][j+2] + (bias ? bias[gc+2] : 0.f);
                v.w = alpha*acc[i][j+3] + (bias ? bias[gc+3] : 0.f);
                *reinterpret_cast<float4*>(cp + j) = v;
            }
        }
    }
}

// ---------------- LN (fp32 out) ----------------
__global__ void ln_kernel(const float* __restrict__ in, float* __restrict__ outp,
                          const float* __restrict__ gam, const float* __restrict__ bet)
{
    __shared__ float sh[8];
    __shared__ float s_mu, s_rs;
    const int row = blockIdx.x, t = threadIdx.x;
    const float* x = in + (long long)row*2048;
    float* y = outp + (long long)row*2048;
    float v[8]; float s = 0.f;
#pragma unroll
    for (int i = 0; i < 2; i++) {
        float4 f = *reinterpret_cast<const float4*>(x + (t + i*256)*4);
        v[i*4+0]=f.x; v[i*4+1]=f.y; v[i*4+2]=f.z; v[i*4+3]=f.w;
        s += f.x + f.y + f.z + f.w;
    }
    s = warpSum(s);
    if ((t&31)==0) sh[t>>5] = s;
    __syncthreads();
    if (t==0) { float tot=0.f;
#pragma unroll
        for (int i=0;i<8;i++) tot+=sh[i]; s_mu = tot*(1.f/2048.f); }
    __syncthreads();
    const float mu = s_mu;
    float q = 0.f;
#pragma unroll
    for (int i=0;i<8;i++){ float d=v[i]-mu; q+=d*d; }
    q = warpSum(q);
    __syncthreads();
    if ((t&31)==0) sh[t>>5] = q;
    __syncthreads();
    if (t==0) { float tot=0.f;
#pragma unroll
        for (int i=0;i<8;i++) tot+=sh[i]; s_rs = rsqrtf(tot*(1.f/2048.f)+1e-5f); }
    __syncthreads();
    const float rs = s_rs;
#pragma unroll
    for (int i=0;i<2;i++) {
        int idx = (t + i*256)*4;
        float4 g4 = *reinterpret_cast<const float4*>(gam+idx);
        float4 b4 = *reinterpret_cast<const float4*>(bet+idx);
        float4 o;
        o.x=(v[i*4+0]-mu)*rs*g4.x+b4.x; o.y=(v[i*4+1]-mu)*rs*g4.y+b4.y;
        o.z=(v[i*4+2]-mu)*rs*g4.z+b4.z; o.w=(v[i*4+3]-mu)*rs*g4.w+b4.w;
        *reinterpret_cast<float4*>(y+idx) = o;
    }
}

// LN -> bf16 hi/lo split (width 2048)
__global__ void ln_split_kernel(const float* __restrict__ in,
                                const float* __restrict__ gam, const float* __restrict__ bet,
                                __nv_bfloat16* __restrict__ hi, __nv_bfloat16* __restrict__ lo)
{
    __shared__ float sh[8];
    __shared__ float s_mu, s_rs;
    const int row = blockIdx.x, t = threadIdx.x;
    const float* x = in + (long long)row*2048;
    float v[8]; float s = 0.f;
#pragma unroll
    for (int i=0;i<2;i++) {
        float4 f = *reinterpret_cast<const float4*>(x + (t + i*256)*4);
        v[i*4+0]=f.x; v[i*4+1]=f.y; v[i*4+2]=f.z; v[i*4+3]=f.w;
        s += f.x + f.y + f.z + f.w;
    }
    s = warpSum(s);
    if ((t&31)==0) sh[t>>5]=s;
    __syncthreads();
    if (t==0){ float tot=0.f;
#pragma unroll
        for (int i=0;i<8;i++) tot+=sh[i]; s_mu=tot*(1.f/2048.f); }
    __syncthreads();
    const float mu=s_mu;
    float q=0.f;
#pragma unroll
    for (int i=0;i<8;i++){ float d=v[i]-mu; q+=d*d; }
    q=warpSum(q);
    __syncthreads();
    if ((t&31)==0) sh[t>>5]=q;
    __syncthreads();
    if (t==0){ float tot=0.f;
#pragma unroll
        for (int i=0;i<8;i++) tot+=sh[i]; s_rs=rsqrtf(tot*(1.f/2048.f)+1e-5f); }
    __syncthreads();
    const float rs=s_rs;
#pragma unroll
    for (int i=0;i<2;i++) {
        int idx = (t + i*256)*4;
        float4 g4 = *reinterpret_cast<const float4*>(gam+idx);
        float4 b4 = *reinterpret_cast<const float4*>(bet+idx);
        float o0=(v[i*4+0]-mu)*rs*g4.x+b4.x, o1=(v[i*4+1]-mu)*rs*g4.y+b4.y;
        float o2=(v[i*4+2]-mu)*rs*g4.z+b4.z, o3=(v[i*4+3]-mu)*rs*g4.w+b4.w;
        unsigned short h0,h1,h2,h3,l0,l1,l2,l3;
        bsplit(o0,h0,l0); bsplit(o1,h1,l1); bsplit(o2,h2,l2); bsplit(o3,h3,l3);
        uint2 hw, lw;
        hw.x=(uint32_t)h0|((uint32_t)h1<<16); hw.y=(uint32_t)h2|((uint32_t)h3<<16);
        lw.x=(uint32_t)l0|((uint32_t)l1<<16); lw.y=(uint32_t)l2|((uint32_t)l3<<16);
        *reinterpret_cast<uint2*>(hi + (long long)row*2048 + idx) = hw;
        *reinterpret_cast<uint2*>(lo + (long long)row*2048 + idx) = lw;
    }
}

// flat fp32 -> bf16 hi/lo
__global__ void split_kernel(const float* __restrict__ in,
                             __nv_bfloat16* __restrict__ hi, __nv_bfloat16* __restrict__ lo,
                             long long n4)
{
    long long i = (long long)blockIdx.x*blockDim.x + threadIdx.x;
    if (i >= n4) return;
    float4 v = reinterpret_cast<const float4*>(in)[i];
    unsigned short h0,h1,h2,h3,l0,l1,l2,l3;
    bsplit(v.x,h0,l0); bsplit(v.y,h1,l1); bsplit(v.z,h2,l2); bsplit(v.w,h3,l3);
    uint2 hw, lw;
    hw.x=(uint32_t)h0|((uint32_t)h1<<16); hw.y=(uint32_t)h2|((uint32_t)h3<<16);
    lw.x=(uint32_t)l0|((uint32_t)l1<<16); lw.y=(uint32_t)l2|((uint32_t)l3<<16);
    reinterpret_cast<uint2*>(hi)[i] = hw;
    reinterpret_cast<uint2*>(lo)[i] = lw;
}

// batched bf16 pair transpose: [R x C] -> [C x R]
__global__ void tbf16_kernel(const __nv_bfloat16* __restrict__ ih, const __nv_bfloat16* __restrict__ il,
                             __nv_bfloat16* __restrict__ oh, __nv_bfloat16* __restrict__ ol,
                             int R, int C, long long sS, long long sD)
{
    __shared__ __nv_bfloat16 th[32][33];
    __shared__ __nv_bfloat16 tl[32][33];
    long long zs = (long long)blockIdx.z*sS, zd = (long long)blockIdx.z*sD;
    int x0 = blockIdx.x*32, y0 = blockIdx.y*32;
    int tx = threadIdx.x, ty = threadIdx.y;
#pragma unroll
    for (int j = 0; j < 32; j += 8) {
        long long src = zs + (long long)(y0+ty+j)*C + x0 + tx;
        th[ty+j][tx] = ih[src]; tl[ty+j][tx] = il[src];
    }
    __syncthreads();
#pragma unroll
    for (int j = 0; j < 32; j += 8) {
        long long dst = zd + (long long)(x0+ty+j)*R + y0 + tx;
        oh[dst] = th[tx][ty+j]; ol[dst] = tl[tx][ty+j];
    }
}

// fp32 [R x C] -> transposed bf16 hi/lo [C x R]
__global__ void tsplit32_kernel(const float* __restrict__ in,
                                __nv_bfloat16* __restrict__ hi, __nv_bfloat16* __restrict__ lo,
                                int R, int C)
{
    __shared__ float tile[32][33];
    int x0 = blockIdx.x*32, y0 = blockIdx.y*32;
    int tx = threadIdx.x, ty = threadIdx.y;
#pragma unroll
    for (int j = 0; j < 32; j += 8)
        tile[ty+j][tx] = in[(long long)(y0+ty+j)*C + x0 + tx];
    __syncthreads();
#pragma unroll
    for (int j = 0; j < 32; j += 8) {
        float v = tile[tx][ty+j];
        unsigned short h, l;
        bsplit(v, h, l);
        long long dst = (long long)(x0+ty+j)*R + y0 + tx;
        hi[dst] = __ushort_as_bfloat16(h);
        lo[dst] = __ushort_as_bfloat16(l);
    }
}

// ---------------- pe / folds / softmax ----------------
__global__ void pe_kernel(float* __restrict__ pe)
{
    const int pos = blockIdx.x, r = pos>>5, cc = pos&31, t = threadIdx.x;
    const float k = -9.210340371976184f / 512.f;
#pragma unroll
    for (int i=0;i<8;i++) {
        int e = t + i*256;
        int p = (e < 1024) ? r : cc;
        int ee = e & 1023;
        float val;
        if (ee < 512) val = sinf((float)p * expf((float)ee*k));
        else          val = cosf((float)p * expf((float)(ee-512)*k));
        pe[(long long)pos*2048 + e] = val;
    }
}

__global__ void c_kernel(const float* __restrict__ qh, const float* __restrict__ bk,
                         float* __restrict__ cvec)
{
    int hq = blockIdx.x*blockDim.x + threadIdx.x;
    if (hq >= 1024) return;
    int h = hq>>6, q = hq&63;
    const float* qr = qh + (long long)q*2048 + h*128;
    const float* br = bk + h*128;
    float s = 0.f;
#pragma unroll 8
    for (int d = 0; d < 128; d++) s += qr[d]*br[d];
    cvec[hq] = s * 0.08838834764831845f;
}

__global__ void bo2_kernel(const float* __restrict__ wo, const float* __restrict__ bv,
                           const float* __restrict__ bo, float* __restrict__ bo2)
{
    int gid = blockIdx.x*blockDim.x + threadIdx.x;
    int f = gid>>5, lane = gid&31;
    if (f >= 2048) return;
    const float* wr = wo + (long long)f*2048;
    float s = 0.f;
    for (int g = lane; g < 2048; g += 32) s += wr[g]*bv[g];
    s = warpSum(s);
    if (lane == 0) bo2[f] = bo[f] + s;
}

__global__ void softmax_split_kernel(const float* __restrict__ S, const float* __restrict__ P,
                                     const float* __restrict__ cvec, const int* __restrict__ tgt,
                                     __nv_bfloat16* __restrict__ Sh, __nv_bfloat16* __restrict__ Sl)
{
    __shared__ float sh[4];
    __shared__ float s_mx, s_inv;
    const int hq = blockIdx.x, b = blockIdx.y, t = threadIdx.x;
    int hh = tgt[2*b];
    int ww = tgt[2*b+1]; ww = min(max(ww,1),32);
    const int hw = hh*ww;
    const long long ro = (long long)(b*1024 + hq)*1024;
    const float* row = S + ro;
    const float* Pr = P + (long long)hq*1024;
    const float cv = cvec[hq];
    float vals[8]; float mx = -3.4e38f;
#pragma unroll
    for (int i = 0; i < 8; i++) {
        int l = t + i*128;
        float s;
        if (l < hw) {
            int r0 = l/ww, cc = l - r0*ww;
            int r = r0 > 31 ? 31 : r0;
            s = row[l] + Pr[r*32+cc] + cv;
        } else s = -1e9f;
        vals[i] = s; mx = fmaxf(mx, s);
    }
    mx = warpMax(mx);
    if ((t&31)==0) sh[t>>5]=mx;
    __syncthreads();
    if (t==0) s_mx = fmaxf(fmaxf(sh[0],sh[1]),fmaxf(sh[2],sh[3]));
    __syncthreads();
    mx = s_mx;
    float sum = 0.f;
#pragma unroll
    for (int i = 0; i < 8; i++) { float e = expf(vals[i]-mx); vals[i] = e; sum += e; }
    sum = warpSum(sum);
    __syncthreads();
    if ((t&31)==0) sh[t>>5]=sum;
    __syncthreads();
    if (t==0) s_inv = 1.f/(sh[0]+sh[1]+sh[2]+sh[3]);
    __syncthreads();
    const float inv = s_inv;
#pragma unroll
    for (int i = 0; i < 8; i++) {
        int l = t + i*128;
        unsigned short h, lo;
        bsplit(vals[i]*inv, h, lo);
        Sh[ro+l] = __ushort_as_bfloat16(h);
        Sl[ro+l] = __ushort_as_bfloat16(lo);
    }
}

// ---------------- launch ----------------
extern "C" void kernel_launch(void* const* d_in, const int* in_sizes, int n_in,
                              void* d_out, int out_size)
{
    (void)in_sizes; (void)n_in; (void)out_size;
    const float* img       = (const float*)d_in[0];
    const int*   tgt       = (const int*)  d_in[1];
    const float* query     = (const float*)d_in[2];
    const float* kv_w      = (const float*)d_in[3];
    const float* ln_q_g    = (const float*)d_in[4];
    const float* ln_q_b    = (const float*)d_in[5];
    const float* ln_kv_g   = (const float*)d_in[6];
    const float* ln_kv_b   = (const float*)d_in[7];
    const float* ln_post_g = (const float*)d_in[8];
    const float* ln_post_b = (const float*)d_in[9];
    const float* wq        = (const float*)d_in[10];
    const float* bq        = (const float*)d_in[11];
    const float* wk        = (const float*)d_in[12];
    const float* bk        = (const float*)d_in[13];
    const float* wv        = (const float*)d_in[14];
    const float* bv        = (const float*)d_in[15];
    const float* wo        = (const float*)d_in[16];
    const float* bo        = (const float*)d_in[17];
    const float* proj      = (const float*)d_in[18];
    float* out = (float*)d_out;

    float *pX,*pS,*pT,*pA,*pP,*pPE,*pQln,*pQh,*pC,*pT2,*pO2,*pBo2;
    __nv_bfloat16 *pImgh,*pImgl,*pKwh,*pKwl,*pXh,*pXl,*pXTh,*pXTl,*pSh,*pSl,*pAhh,*pAhl;
    __nv_bfloat16 *pT2h,*pT2l,*pO3h,*pO3l,*pWoh,*pWol,*pPjh,*pPjl;
    cudaGetSymbolAddress((void**)&pX, g_X);   cudaGetSymbolAddress((void**)&pS, g_S);
    cudaGetSymbolAddress((void**)&pT, g_T);   cudaGetSymbolAddress((void**)&pA, g_A);
    cudaGetSymbolAddress((void**)&pP, g_P);   cudaGetSymbolAddress((void**)&pPE, g_pe);
    cudaGetSymbolAddress((void**)&pQln, g_qln); cudaGetSymbolAddress((void**)&pQh, g_qh);
    cudaGetSymbolAddress((void**)&pC, g_c);   cudaGetSymbolAddress((void**)&pT2, g_t2);
    cudaGetSymbolAddress((void**)&pO2, g_o2); cudaGetSymbolAddress((void**)&pBo2, g_bo2);
    cudaGetSymbolAddress((void**)&pImgh, g_imgh); cudaGetSymbolAddress((void**)&pImgl, g_imgl);
    cudaGetSymbolAddress((void**)&pKwh, g_kwh);   cudaGetSymbolAddress((void**)&pKwl, g_kwl);
    cudaGetSymbolAddress((void**)&pXh, g_Xh);     cudaGetSymbolAddress((void**)&pXl, g_Xl);
    cudaGetSymbolAddress((void**)&pXTh, g_XTh);   cudaGetSymbolAddress((void**)&pXTl, g_XTl);
    cudaGetSymbolAddress((void**)&pSh, g_Sh);     cudaGetSymbolAddress((void**)&pSl, g_Sl);
    cudaGetSymbolAddress((void**)&pAhh, g_Ahh);   cudaGetSymbolAddress((void**)&pAhl, g_Ahl);
    cudaGetSymbolAddress((void**)&pT2h, g_t2h);   cudaGetSymbolAddress((void**)&pT2l, g_t2l);
    cudaGetSymbolAddress((void**)&pO3h, g_o3h);   cudaGetSymbolAddress((void**)&pO3l, g_o3l);
    cudaGetSymbolAddress((void**)&pWoh, g_woh);   cudaGetSymbolAddress((void**)&pWol, g_wol);
    cudaGetSymbolAddress((void**)&pPjh, g_pjh);   cudaGetSymbolAddress((void**)&pPjl, g_pjl);

    cudaFuncSetAttribute(mma_gemm, cudaFuncAttributeMaxDynamicSharedMemorySize, MG_SMEM);

    const float INV = 0.08838834764831845f;

    // prologue (query side, pe, folds) — SIMT, small
    pe_kernel<<<1024, 256>>>(pPE);
    ln_kernel<<<64, 256>>>(query, pQln, ln_q_g, ln_q_b);
    sgemm_kernel<64,128,32,8,8,1><<<dim3(16,1,1),128>>>(
        pQln, 2048, wq, 2048, pQh, 2048, 64, 2048, 2048, 1.f, bq, 0,0,0,0,0,0, 1);
    sgemm_kernel<64,128,32,8,8,0><<<dim3(16,1,16),128>>>(
        pQh, 2048, wk, 2048, pA, 2048, 64, 2048, 128, INV, nullptr,
        128,0, (long long)128*2048,0, (long long)64*2048,0, 1);
    c_kernel<<<8,128>>>(pQh, bk, pC);
    bo2_kernel<<<256,256>>>(wo, bv, bo, pBo2);
    sgemm_kernel<128,128,32,8,8,1><<<dim3(8,8,1),256>>>(
        pA, 2048, pPE, 2048, pP, 1024, 1024, 1024, 2048, 1.f, nullptr, 0,0,0,0,0,0, 1);
    split_kernel<<<2048, 256>>>(pA, pAhh, pAhl, (long long)C_HQ*C_E/4);

    // splits for tensor GEMMs
    split_kernel<<<36864, 256>>>(img, pImgh, pImgl, (long long)C_B*C_L*1152/4);
    split_kernel<<<2304, 256>>>(kv_w, pKwh, pKwl, (long long)C_E*1152/4);
    split_kernel<<<4096, 256>>>(wo, pWoh, pWol, (long long)C_E*C_E/4);
    tsplit32_kernel<<<dim3(64,64), dim3(32,8)>>>(proj, pPjh, pPjl, 2048, 2048);

    // X = img @ kv_w^T  [32768 x 2048], K=1152
    mma_gemm<<<dim3(16,256,1), 256, MG_SMEM>>>(
        pImgh, pImgl, 1152, pKwh, pKwl, 1152, pX, 2048, 1152, nullptr, 0,0,0);
    // LN(X) -> bf16 split
    ln_split_kernel<<<32768, 256>>>(pX, ln_kv_g, ln_kv_b, pXh, pXl);
    // XT per batch [e][l]
    tbf16_kernel<<<dim3(64,32,32), dim3(32,8)>>>(pXh, pXl, pXTh, pXTl, 1024, 2048, LE, LE);

    // S[b] = A @ X_b^T  per batch
    mma_gemm<<<dim3(8,8,32), 256, MG_SMEM>>>(
        pAhh, pAhl, 2048, pXh, pXl, 2048, pS, 1024, 2048, nullptr, 0, LE, LHQ);
    // softmax (+pe/bk/mask) -> bf16 split
    softmax_split_kernel<<<dim3(1024,32),128>>>(pS, pP, pC, tgt, pSh, pSl);
    // T[b] = attn_b @ X_b  (NT via XT)
    mma_gemm<<<dim3(16,8,32), 256, MG_SMEM>>>(
        pSh, pSl, 1024, pXTh, pXTl, 1024, pT, 2048, 1024, nullptr, LHQ, LE, LE);

    // per-head V projection (SIMT): t2[b][q] = T[b][h*64+q] @ wv_h^T
    sgemm_kernel<64,128,32,8,8,1><<<dim3(1,1,512),128>>>(
        pT, 2048, wv, 2048, pT2, 2048, 64, 128, 2048, 1.f, nullptr,
        LE, (long long)64*2048, 0, (long long)128*2048, (long long)64*2048, 128, 16);
    // o2 = t2 @ wo^T + bo2
    split_kernel<<<4096, 256>>>(pT2, pT2h, pT2l, (long long)C_B*C_NQ*C_E/4);
    mma_gemm<<<dim3(16,16,1), 256, MG_SMEM>>>(
        pT2h, pT2l, 2048, pWoh, pWol, 2048, pO2, 2048, 2048, pBo2, 0,0,0);
    // LN(o2) -> bf16 split
    ln_split_kernel<<<2048, 256>>>(pO2, ln_post_g, ln_post_b, pO3h, pO3l);
    // out = o3 @ proj  (NT via projT)
    mma_gemm<<<dim3(16,16,1), 256, MG_SMEM>>>(
        pO3h, pO3l, 2048, pPjh, pPjl, 2048, out, 2048, 2048, nullptr, 0,0,0);
}